// round 6
// baseline (speedup 1.0000x reference)
#include <cuda_runtime.h>
#include <cuda_bf16.h>
#include <math.h>

// Problem constants
#define TDIM 4096          // B*S tokens
#define HDIM 1024          // hidden
#define EDIM 8             // experts
#define FDIM 2048          // ffn
#define KSEL 2             // top-k
#define NROWS (TDIM*KSEL)  // 8192 dispatch rows

// GEMM tiling
#define BM 64
#define BN 64
#define BK 16

// ---------------- device scratch (allocation-free) ----------------
__device__ float g_glu[(size_t)NROWS * FDIM];    // 64 MB: GLU activations per dispatch row (list order)
__device__ float g_pairs[(size_t)NROWS * HDIM];  // 32 MB: expert outputs per (token,slot) row
__device__ int   g_eid[NROWS];                   // expert id per (t*2+k)
__device__ float g_gate[NROWS];                  // gate per (t*2+k)
__device__ int   g_list[NROWS];                  // per-expert contiguous lists of row ids (t*2+k)
__device__ int   g_freq[EDIM];
__device__ int   g_cursor[EDIM];
__device__ int   g_offsets[EDIM + 1];
__device__ float g_psum[EDIM];
__device__ float g_lsesq;

// ---------------- reset counters (graph replays!) ----------------
__global__ void zero_kernel() {
    int i = threadIdx.x;
    if (i < EDIM) { g_freq[i] = 0; g_cursor[i] = 0; g_psum[i] = 0.f; }
    if (i == 0) g_lsesq = 0.f;
}

// ---------------- router: logits, top-2, gates, loss partials ----------------
// one warp per token, 8 warps per block
__global__ void router_kernel(const float* __restrict__ x,
                              const float* __restrict__ wr) {
    __shared__ float s_p[EDIM];
    __shared__ float s_lsesq;
    int tid = threadIdx.x;
    if (tid < EDIM) s_p[tid] = 0.f;
    if (tid == 0) s_lsesq = 0.f;
    __syncthreads();

    int t = blockIdx.x * 8 + (tid >> 5);
    int lane = tid & 31;

    float acc[8] = {0.f,0.f,0.f,0.f,0.f,0.f,0.f,0.f};
    const float* xp = x + (size_t)t * HDIM;
    for (int h = lane; h < HDIM; h += 32) {
        float xv = xp[h];
        float4 w0 = *(const float4*)(wr + h * 8);
        float4 w1 = *(const float4*)(wr + h * 8 + 4);
        acc[0] += xv * w0.x; acc[1] += xv * w0.y;
        acc[2] += xv * w0.z; acc[3] += xv * w0.w;
        acc[4] += xv * w1.x; acc[5] += xv * w1.y;
        acc[6] += xv * w1.z; acc[7] += xv * w1.w;
    }
#pragma unroll
    for (int e = 0; e < 8; e++) {
#pragma unroll
        for (int o = 16; o > 0; o >>= 1)
            acc[e] += __shfl_down_sync(0xffffffffu, acc[e], o);
    }

    if (lane == 0) {
        float m = acc[0];
#pragma unroll
        for (int e = 1; e < 8; e++) m = fmaxf(m, acc[e]);
        float ex[8], sum = 0.f;
#pragma unroll
        for (int e = 0; e < 8; e++) { ex[e] = expf(acc[e] - m); sum += ex[e]; }
        float inv = 1.f / sum;
        float lse = m + logf(sum);

        // top-2, first-occurrence tie-break (matches jax.lax.top_k)
        int i0 = 0;
#pragma unroll
        for (int e = 1; e < 8; e++) if (acc[e] > acc[i0]) i0 = e;
        int i1 = (i0 == 0) ? 1 : 0;
#pragma unroll
        for (int e = 0; e < 8; e++) if (e != i0 && acc[e] > acc[i1]) i1 = e;

        float d = expf(acc[i1] - acc[i0]);   // v1 <= v0 -> stable
        float g0 = 1.f / (1.f + d);
        float g1 = d / (1.f + d);

        g_eid[2 * t]     = i0;  g_eid[2 * t + 1]  = i1;
        g_gate[2 * t]    = g0;  g_gate[2 * t + 1] = g1;
        atomicAdd(&g_freq[i0], 1);
        atomicAdd(&g_freq[i1], 1);
#pragma unroll
        for (int e = 0; e < 8; e++) atomicAdd(&s_p[e], ex[e] * inv);
        atomicAdd(&s_lsesq, lse * lse);
    }
    __syncthreads();
    if (tid < EDIM) atomicAdd(&g_psum[tid], s_p[tid]);
    if (tid == 0)   atomicAdd(&g_lsesq, s_lsesq);
}

// ---------------- tiny scan + scatter to build per-expert lists ----------------
__global__ void scan_kernel() {
    if (threadIdx.x == 0) {
        int s = 0;
        for (int e = 0; e < EDIM; e++) { g_offsets[e] = s; s += g_freq[e]; }
        g_offsets[EDIM] = s;
    }
}

__global__ void scatter_kernel() {
    int r = blockIdx.x * blockDim.x + threadIdx.x;
    if (r < NROWS) {
        int e = g_eid[r];
        int pos = atomicAdd(&g_cursor[e], 1);
        g_list[g_offsets[e] + pos] = r;
    }
}

// ---------------- GEMM1: h = x[tok] @ w_in[e], fused GLU -> g_glu ----------------
// grid: (FDIM/BN, maxRowTiles, E); block: 256 threads; 4x4 per-thread tile, dual acc for GLU halves
__global__ void __launch_bounds__(256) gemm1_kernel(const float* __restrict__ x,
                                                    const float* __restrict__ w_in) {
    const int e = blockIdx.z;
    const int cnt = g_freq[e];
    const int row0 = blockIdx.y * BM;
    if (row0 >= cnt) return;
    const int off = g_offsets[e];
    const int col0 = blockIdx.x * BN;

    __shared__ float As[BM][BK];
    __shared__ float Bs1[BK][BN];
    __shared__ float Bs2[BK][BN];
    __shared__ int s_tok[BM];

    const int tid = threadIdx.x;
    if (tid < BM) {
        int r = row0 + tid;
        s_tok[tid] = (r < cnt) ? (g_list[off + r] >> 1) : -1;
    }
    __syncthreads();

    const int a_row = tid >> 2;          // 0..63
    const int a_k   = (tid & 3) << 2;    // 0,4,8,12
    const int b_k   = tid >> 4;          // 0..15
    const int b_c   = (tid & 15) << 2;   // 0..60
    const int ty    = tid >> 4;          // 0..15 -> rows ty*4..+3
    const int tx    = tid & 15;          // cols tx*4..+3

    const int t_a = s_tok[a_row];
    const float* xp = x + ((t_a >= 0) ? ((size_t)t_a * HDIM + a_k) : 0);
    const float* wb = w_in + (size_t)e * HDIM * (2 * FDIM) + col0;

    float acc1[4][4] = {};
    float acc2[4][4] = {};

    for (int k0 = 0; k0 < HDIM; k0 += BK) {
        float4 av = make_float4(0.f, 0.f, 0.f, 0.f);
        if (t_a >= 0) av = *(const float4*)(xp + k0);
        *(float4*)&As[a_row][a_k] = av;

        const float* wp = wb + (size_t)(k0 + b_k) * (2 * FDIM) + b_c;
        *(float4*)&Bs1[b_k][b_c] = *(const float4*)wp;
        *(float4*)&Bs2[b_k][b_c] = *(const float4*)(wp + FDIM);
        __syncthreads();

#pragma unroll
        for (int k = 0; k < BK; k++) {
            float a[4];
#pragma unroll
            for (int i = 0; i < 4; i++) a[i] = As[ty * 4 + i][k];
            float4 v1 = *(const float4*)&Bs1[k][tx * 4];
            float4 v2 = *(const float4*)&Bs2[k][tx * 4];
            float b1[4] = {v1.x, v1.y, v1.z, v1.w};
            float b2[4] = {v2.x, v2.y, v2.z, v2.w};
#pragma unroll
            for (int i = 0; i < 4; i++)
#pragma unroll
                for (int j = 0; j < 4; j++) {
                    acc1[i][j] += a[i] * b1[j];
                    acc2[i][j] += a[i] * b2[j];
                }
        }
        __syncthreads();
    }

#pragma unroll
    for (int i = 0; i < 4; i++) {
        int r = row0 + ty * 4 + i;
        if (r < cnt) {
            size_t p = (size_t)(off + r);
            float4 o;
            {
                float aa = acc1[i][0];
                o.x = (aa / (1.f + expf(-aa))) * acc2[i][0];
                aa = acc1[i][1];
                o.y = (aa / (1.f + expf(-aa))) * acc2[i][1];
                aa = acc1[i][2];
                o.z = (aa / (1.f + expf(-aa))) * acc2[i][2];
                aa = acc1[i][3];
                o.w = (aa / (1.f + expf(-aa))) * acc2[i][3];
            }
            *(float4*)&g_glu[p * FDIM + col0 + tx * 4] = o;
        }
    }
}

// ---------------- GEMM2: out = glu @ w_out[e], fused gate scale -> g_pairs ----------------
__global__ void __launch_bounds__(256) gemm2_kernel(const float* __restrict__ w_out) {
    const int e = blockIdx.z;
    const int cnt = g_freq[e];
    const int row0 = blockIdx.y * BM;
    if (row0 >= cnt) return;
    const int off = g_offsets[e];
    const int col0 = blockIdx.x * BN;

    __shared__ float As[BM][BK];
    __shared__ float Bs[BK][BN];
    __shared__ int s_dst[BM];

    const int tid = threadIdx.x;
    if (tid < BM) {
        int r = row0 + tid;
        s_dst[tid] = (r < cnt) ? g_list[off + r] : -1;
    }
    __syncthreads();

    const int a_row = tid >> 2;
    const int a_k   = (tid & 3) << 2;
    const int b_k   = tid >> 4;
    const int b_c   = (tid & 15) << 2;
    const int ty    = tid >> 4;
    const int tx    = tid & 15;

    const bool a_valid = (row0 + a_row) < cnt;
    const float* ap = g_glu + (size_t)(off + row0 + a_row) * FDIM + a_k;
    const float* wb = w_out + (size_t)e * FDIM * HDIM + col0;

    float acc[4][4] = {};

    for (int k0 = 0; k0 < FDIM; k0 += BK) {
        float4 av = make_float4(0.f, 0.f, 0.f, 0.f);
        if (a_valid) av = *(const float4*)(ap + k0);
        *(float4*)&As[a_row][a_k] = av;

        *(float4*)&Bs[b_k][b_c] =
            *(const float4*)(wb + (size_t)(k0 + b_k) * HDIM + b_c);
        __syncthreads();

#pragma unroll
        for (int k = 0; k < BK; k++) {
            float a[4];
#pragma unroll
            for (int i = 0; i < 4; i++) a[i] = As[ty * 4 + i][k];
            float4 v = *(const float4*)&Bs[k][tx * 4];
            float b[4] = {v.x, v.y, v.z, v.w};
#pragma unroll
            for (int i = 0; i < 4; i++)
#pragma unroll
                for (int j = 0; j < 4; j++)
                    acc[i][j] += a[i] * b[j];
        }
        __syncthreads();
    }

#pragma unroll
    for (int i = 0; i < 4; i++) {
        int r = row0 + ty * 4 + i;
        if (r < cnt) {
            int dst = s_dst[ty * 4 + i];
            float g = g_gate[dst];
            float4 o;
            o.x = acc[i][0] * g; o.y = acc[i][1] * g;
            o.z = acc[i][2] * g; o.w = acc[i][3] * g;
            *(float4*)&g_pairs[(size_t)dst * HDIM + col0 + tx * 4] = o;
        }
    }
}

// ---------------- combine: y[t] = pairs[2t] + pairs[2t+1] + bias (deterministic) ----------------
__global__ void combine_kernel(float* __restrict__ out, const float* __restrict__ bias) {
    int i = blockIdx.x * blockDim.x + threadIdx.x;  // float4 index over T*H/4
    if (i < TDIM * HDIM / 4) {
        int t = i >> 8;      // H/4 = 256
        int c4 = i & 255;
        const float4* p4 = (const float4*)g_pairs;
        float4 a = p4[(size_t)(2 * t) * 256 + c4];
        float4 b = p4[(size_t)(2 * t) * 256 + 256 + c4];
        float4 bs = ((const float4*)bias)[c4];
        float4 o;
        o.x = a.x + b.x + bs.x; o.y = a.y + b.y + bs.y;
        o.z = a.z + b.z + bs.z; o.w = a.w + b.w + bs.w;
        ((float4*)out)[i] = o;
    }
}

// ---------------- loss finalize ----------------
__global__ void loss_kernel(float* __restrict__ out, int out_size) {
    if (threadIdx.x == 0 && blockIdx.x == 0) {
        float s = 0.f;
        for (int e = 0; e < EDIM; e++) s += g_psum[e] * (float)g_freq[e];
        // p_e = psum/T (since sum_e psum = T), f_e = freq/(T*K)
        float loss = (float)EDIM * s / ((float)TDIM * (float)(TDIM * KSEL))
                   + 0.1f * g_lsesq / (float)TDIM;
        if (out_size > TDIM * HDIM) out[TDIM * HDIM] = loss;
    }
}

// ---------------- launch ----------------
extern "C" void kernel_launch(void* const* d_in, const int* in_sizes, int n_in,
                              void* d_out, int out_size) {
    const float* x        = (const float*)d_in[0];
    const float* w_router = (const float*)d_in[1];
    const float* w_in     = (const float*)d_in[2];
    const float* w_out    = (const float*)d_in[3];
    const float* bias     = (const float*)d_in[4];
    float* out = (float*)d_out;

    zero_kernel<<<1, 32>>>();
    router_kernel<<<TDIM / 8, 256>>>(x, w_router);
    scan_kernel<<<1, 32>>>();
    scatter_kernel<<<NROWS / 256, 256>>>();

    dim3 g1(FDIM / BN, TDIM / BM, EDIM);   // (32, 64, 8) — worst-case rows per expert = T
    gemm1_kernel<<<g1, 256>>>(x, w_in);

    dim3 g2(HDIM / BN, TDIM / BM, EDIM);   // (16, 64, 8)
    gemm2_kernel<<<g2, 256>>>(w_out);

    combine_kernel<<<(TDIM * HDIM / 4 + 255) / 256, 256>>>(out, bias);
    loss_kernel<<<1, 32>>>(out, out_size);
}

// round 9
// speedup vs baseline: 3.6046x; 3.6046x over previous
#include <cuda_runtime.h>
#include <math.h>
#include <stdint.h>

// Problem constants
#define TDIM 4096          // B*S tokens
#define HDIM 1024          // hidden
#define EDIM 8             // experts
#define FDIM 2048          // ffn
#define KSEL 2             // top-k
#define NROWS (TDIM*KSEL)  // 8192 dispatch rows

// ==================== device scratch (allocation-free) ====================
__device__ float g_glu[(size_t)NROWS * FDIM];    // 64 MB GLU activations (list order)
__device__ float g_pairs[(size_t)NROWS * HDIM];  // 32 MB expert outputs per (token,slot)
__device__ int   g_eid[NROWS];
__device__ float g_gate[NROWS];
__device__ int   g_list[NROWS];
__device__ int   g_freq[EDIM];
__device__ int   g_cursor[EDIM];
__device__ int   g_offsets[EDIM + 1];
__device__ float g_psum[EDIM];
__device__ float g_lsesq;

// ==================== PTX helpers (sm_80-baseline features only!) ====================
__device__ __forceinline__ uint32_t smem_u32(const void* p) {
    uint32_t a;
    asm("{ .reg .u64 t; cvta.to.shared.u64 t, %1; cvt.u32.u64 %0, t; }" : "=r"(a) : "l"(p));
    return a;
}
__device__ __forceinline__ void cp16(uint32_t dst, const void* src) {
    asm volatile("cp.async.cg.shared.global [%0], [%1], 16;" :: "r"(dst), "l"(src));
}
#define CP_COMMIT() asm volatile("cp.async.commit_group;" ::: "memory")
#define CP_WAIT1()  asm volatile("cp.async.wait_group 1;" ::: "memory")
#define CP_WAIT0()  asm volatile("cp.async.wait_group 0;" ::: "memory")

__device__ __forceinline__ uint32_t f2tf32(float f) {
    uint32_t r;
    asm("cvt.rna.tf32.f32 %0, %1;" : "=r"(r) : "f"(f));
    return r;
}
__device__ __forceinline__ void mma_tf32(float* d, const uint32_t* a, const uint32_t* b) {
    asm volatile(
        "mma.sync.aligned.m16n8k8.row.col.f32.tf32.tf32.f32 "
        "{%0,%1,%2,%3}, {%4,%5,%6,%7}, {%8,%9}, {%0,%1,%2,%3};"
        : "+f"(d[0]), "+f"(d[1]), "+f"(d[2]), "+f"(d[3])
        : "r"(a[0]), "r"(a[1]), "r"(a[2]), "r"(a[3]), "r"(b[0]), "r"(b[1]));
}

// Shared-memory tile geometry (padded for conflict-free fragment loads)
#define ASTR 36     // A row stride (floats): bank = (4g+tq)%32 -> conflict-free
#define BSTR 136    // B row stride (floats): bank = (8tq+g)%32 -> conflict-free
#define SM_AS 512
#define SM_BS (SM_AS + 2*128*ASTR*4)               // 512 + 36864 = 37376
#define GEMM_SMEM (SM_BS + 2*32*BSTR*4)            // + 34816 = 72192

// ==================== reset counters (graph replays) ====================
__global__ void zero_kernel() {
    int i = threadIdx.x;
    if (i < EDIM) { g_freq[i] = 0; g_cursor[i] = 0; g_psum[i] = 0.f; }
    if (i == 0) g_lsesq = 0.f;
}

// ==================== router ====================
__global__ void router_kernel(const float* __restrict__ x,
                              const float* __restrict__ wr) {
    __shared__ float s_p[EDIM];
    __shared__ float s_lsesq;
    int tid = threadIdx.x;
    if (tid < EDIM) s_p[tid] = 0.f;
    if (tid == 0) s_lsesq = 0.f;
    __syncthreads();

    int t = blockIdx.x * 8 + (tid >> 5);
    int lane = tid & 31;

    float acc[8] = {0.f,0.f,0.f,0.f,0.f,0.f,0.f,0.f};
    const float* xp = x + (size_t)t * HDIM;
    for (int h = lane; h < HDIM; h += 32) {
        float xv = xp[h];
        float4 w0 = *(const float4*)(wr + h * 8);
        float4 w1 = *(const float4*)(wr + h * 8 + 4);
        acc[0] += xv * w0.x; acc[1] += xv * w0.y;
        acc[2] += xv * w0.z; acc[3] += xv * w0.w;
        acc[4] += xv * w1.x; acc[5] += xv * w1.y;
        acc[6] += xv * w1.z; acc[7] += xv * w1.w;
    }
#pragma unroll
    for (int e = 0; e < 8; e++)
#pragma unroll
        for (int o = 16; o > 0; o >>= 1)
            acc[e] += __shfl_down_sync(0xffffffffu, acc[e], o);

    if (lane == 0) {
        float m = acc[0];
#pragma unroll
        for (int e = 1; e < 8; e++) m = fmaxf(m, acc[e]);
        float ex[8], sum = 0.f;
#pragma unroll
        for (int e = 0; e < 8; e++) { ex[e] = expf(acc[e] - m); sum += ex[e]; }
        float inv = 1.f / sum;
        float lse = m + logf(sum);

        int i0 = 0;
#pragma unroll
        for (int e = 1; e < 8; e++) if (acc[e] > acc[i0]) i0 = e;
        int i1 = (i0 == 0) ? 1 : 0;
#pragma unroll
        for (int e = 0; e < 8; e++) if (e != i0 && acc[e] > acc[i1]) i1 = e;

        float d = expf(acc[i1] - acc[i0]);
        float g0 = 1.f / (1.f + d);
        float g1 = d / (1.f + d);

        g_eid[2 * t]     = i0;  g_eid[2 * t + 1]  = i1;
        g_gate[2 * t]    = g0;  g_gate[2 * t + 1] = g1;
        atomicAdd(&g_freq[i0], 1);
        atomicAdd(&g_freq[i1], 1);
#pragma unroll
        for (int e = 0; e < 8; e++) atomicAdd(&s_p[e], ex[e] * inv);
        atomicAdd(&s_lsesq, lse * lse);
    }
    __syncthreads();
    if (tid < EDIM) atomicAdd(&g_psum[tid], s_p[tid]);
    if (tid == 0)   atomicAdd(&g_lsesq, s_lsesq);
}

__global__ void scan_kernel() {
    if (threadIdx.x == 0) {
        int s = 0;
        for (int e = 0; e < EDIM; e++) { g_offsets[e] = s; s += g_freq[e]; }
        g_offsets[EDIM] = s;
    }
}

__global__ void scatter_kernel() {
    int r = blockIdx.x * blockDim.x + threadIdx.x;
    if (r < NROWS) {
        int e = g_eid[r];
        int pos = atomicAdd(&g_cursor[e], 1);
        g_list[g_offsets[e] + pos] = r;
    }
}

// ==================== GEMM1 tile loaders ====================
// A: 128 gathered token rows x 32 K-floats. B: 32 K-rows x 128 cols where
// cols [0,32)=a[n0..], [32,64)=gv[n0..], [64,96)=a[n0+32..], [96,128)=gv[n0+32..]
__device__ __forceinline__ void g1_load(const float* __restrict__ x,
                                        const float* __restrict__ w1,
                                        const int* s_tok,
                                        uint32_t as_u, uint32_t bs_u,
                                        int tid, int n0, int c, int st) {
    const int k0 = c * 32;
#pragma unroll
    for (int i = 0; i < 8; i++) {
        int idx = tid + i * 128;
        int row = idx >> 3, seg = idx & 7;
        const float* src = x + (size_t)s_tok[row] * HDIM + k0 + seg * 4;
        cp16(as_u + (uint32_t)((st * 128 * ASTR + row * ASTR + seg * 4) * 4), src);
    }
#pragma unroll
    for (int i = 0; i < 8; i++) {
        int idx = tid + i * 128;
        int kr = idx >> 5, j = (idx & 31) * 4;
        int half = (j >> 5) & 1, blk = j >> 6, cloc = j & 31;
        int wcol = n0 + blk * 32 + cloc + (half ? FDIM : 0);
        const float* src = w1 + (size_t)(k0 + kr) * (2 * FDIM) + wcol;
        cp16(bs_u + (uint32_t)((st * 32 * BSTR + kr * BSTR + j) * 4), src);
    }
    CP_COMMIT();
}

__device__ __forceinline__ void g2_load(const float* __restrict__ w2,
                                        int off, int row0, int rlim,
                                        uint32_t as_u, uint32_t bs_u,
                                        int tid, int n1, int c, int st) {
    const int k0 = c * 32;
#pragma unroll
    for (int i = 0; i < 8; i++) {
        int idx = tid + i * 128;
        int row = idx >> 3, seg = idx & 7;
        int rr = (row < rlim) ? row : (rlim - 1);
        const float* src = g_glu + (size_t)(off + row0 + rr) * FDIM + k0 + seg * 4;
        cp16(as_u + (uint32_t)((st * 128 * ASTR + row * ASTR + seg * 4) * 4), src);
    }
#pragma unroll
    for (int i = 0; i < 8; i++) {
        int idx = tid + i * 128;
        int kr = idx >> 5, j = (idx & 31) * 4;
        const float* src = w2 + (size_t)(k0 + kr) * HDIM + n1 + j;
        cp16(bs_u + (uint32_t)((st * 32 * BSTR + kr * BSTR + j) * 4), src);
    }
    CP_COMMIT();
}

// ==================== GEMM1: x[tok] @ w_in[e], fused GLU ====================
// CTA tile 128 rows x (64 a-cols + 64 gv-cols). 4 warps of 64x64.
__global__ void __launch_bounds__(128) gemm1_mma(const float* __restrict__ x,
                                                 const float* __restrict__ w_in) {
    const int e = blockIdx.z;
    const int cnt = g_freq[e];
    const int row0 = blockIdx.y * 128;
    if (row0 >= cnt) return;
    const int off = g_offsets[e];
    const int n0 = blockIdx.x * 64;

    extern __shared__ char smem[];
    int* s_tok = (int*)smem;
    float* As = (float*)(smem + SM_AS);
    float* Bs = (float*)(smem + SM_BS);
    const uint32_t as_u = smem_u32(As), bs_u = smem_u32(Bs);

    const int tid = threadIdx.x;
    if (tid < 128) {
        int r = row0 + tid;
        s_tok[tid] = g_list[off + ((r < cnt) ? r : (cnt - 1))] >> 1;
    }
    __syncthreads();

    const float* w1 = w_in + (size_t)e * HDIM * (2 * FDIM);

    const int lane = tid & 31, wid = tid >> 5;
    const int wm = wid & 1, wn = wid >> 1;
    const int g = lane >> 2, tq = lane & 3;

    float acc[4][8][4];
#pragma unroll
    for (int i = 0; i < 4; i++)
#pragma unroll
        for (int f = 0; f < 8; f++)
#pragma unroll
            for (int q = 0; q < 4; q++) acc[i][f][q] = 0.f;

    const int NCH = HDIM / 32;  // 32
    g1_load(x, w1, s_tok, as_u, bs_u, tid, n0, 0, 0);
    g1_load(x, w1, s_tok, as_u, bs_u, tid, n0, 1, 1);
    CP_WAIT1();
    __syncthreads();

    for (int c = 0; c < NCH; c++) {
        const int st = c & 1;
        const float* Ast = As + st * 128 * ASTR;
        const float* Bst = Bs + st * 32 * BSTR;
#pragma unroll
        for (int ks = 0; ks < 4; ks++) {
            uint32_t af[4][4];
#pragma unroll
            for (int i = 0; i < 4; i++) {
                const float* ap = Ast + (wm * 64 + i * 16 + g) * ASTR + ks * 8 + tq;
                af[i][0] = f2tf32(ap[0]);
                af[i][1] = f2tf32(ap[8 * ASTR]);
                af[i][2] = f2tf32(ap[4]);
                af[i][3] = f2tf32(ap[8 * ASTR + 4]);
            }
            uint32_t bf[8][2];
#pragma unroll
            for (int f = 0; f < 8; f++) {
                const float* bp = Bst + (ks * 8 + tq) * BSTR + wn * 64 + f * 8 + g;
                bf[f][0] = f2tf32(bp[0]);
                bf[f][1] = f2tf32(bp[4 * BSTR]);
            }
#pragma unroll
            for (int i = 0; i < 4; i++)
#pragma unroll
                for (int f = 0; f < 8; f++)
                    mma_tf32(acc[i][f], af[i], bf[f]);
        }
        __syncthreads();
        if (c + 2 < NCH) g1_load(x, w1, s_tok, as_u, bs_u, tid, n0, c + 2, st);
        if (c + 1 < NCH) {
            if (c + 2 < NCH) CP_WAIT1(); else CP_WAIT0();
            __syncthreads();
        }
    }

    // epilogue: GLU. warp wn covers a-cols n0+wn*32.. paired with gv (n-frags f and f+4)
#pragma unroll
    for (int i = 0; i < 4; i++) {
        const int rbase = wm * 64 + i * 16 + g;
#pragma unroll
        for (int hr = 0; hr < 2; hr++) {
            const int r = rbase + hr * 8;
            if (row0 + r < cnt) {
                float* dst = g_glu + (size_t)(off + row0 + r) * FDIM + n0 + wn * 32;
#pragma unroll
                for (int f = 0; f < 4; f++) {
                    float a0 = acc[i][f][hr * 2], a1 = acc[i][f][hr * 2 + 1];
                    float v0 = acc[i][f + 4][hr * 2], v1 = acc[i][f + 4][hr * 2 + 1];
                    float2 o;
                    o.x = (a0 / (1.f + __expf(-a0))) * v0;
                    o.y = (a1 / (1.f + __expf(-a1))) * v1;
                    *(float2*)(dst + f * 8 + 2 * tq) = o;
                }
            }
        }
    }
}

// ==================== GEMM2: glu @ w_out[e], fused gate-scale scatter ====================
__global__ void __launch_bounds__(128) gemm2_mma(const float* __restrict__ w_out) {
    const int e = blockIdx.z;
    const int cnt = g_freq[e];
    const int row0 = blockIdx.y * 128;
    if (row0 >= cnt) return;
    const int off = g_offsets[e];
    const int n1 = blockIdx.x * 128;
    const int rlim = cnt - row0;

    extern __shared__ char smem[];
    int* s_dst = (int*)smem;
    float* As = (float*)(smem + SM_AS);
    float* Bs = (float*)(smem + SM_BS);
    const uint32_t as_u = smem_u32(As), bs_u = smem_u32(Bs);

    const int tid = threadIdx.x;
    if (tid < 128) {
        int r = row0 + tid;
        s_dst[tid] = g_list[off + ((r < cnt) ? r : (cnt - 1))];
    }
    __syncthreads();

    const float* w2 = w_out + (size_t)e * FDIM * HDIM;

    const int lane = tid & 31, wid = tid >> 5;
    const int wm = wid & 1, wn = wid >> 1;
    const int g = lane >> 2, tq = lane & 3;

    float acc[4][8][4];
#pragma unroll
    for (int i = 0; i < 4; i++)
#pragma unroll
        for (int f = 0; f < 8; f++)
#pragma unroll
            for (int q = 0; q < 4; q++) acc[i][f][q] = 0.f;

    const int NCH = FDIM / 32;  // 64
    g2_load(w2, off, row0, rlim, as_u, bs_u, tid, n1, 0, 0);
    g2_load(w2, off, row0, rlim, as_u, bs_u, tid, n1, 1, 1);
    CP_WAIT1();
    __syncthreads();

    for (int c = 0; c < NCH; c++) {
        const int st = c & 1;
        const float* Ast = As + st * 128 * ASTR;
        const float* Bst = Bs + st * 32 * BSTR;
#pragma unroll
        for (int ks = 0; ks < 4; ks++) {
            uint32_t af[4][4];
#pragma unroll
            for (int i = 0; i < 4; i++) {
                const float* ap = Ast + (wm * 64 + i * 16 + g) * ASTR + ks * 8 + tq;
                af[i][0] = f2tf32(ap[0]);
                af[i][1] = f2tf32(ap[8 * ASTR]);
                af[i][2] = f2tf32(ap[4]);
                af[i][3] = f2tf32(ap[8 * ASTR + 4]);
            }
            uint32_t bf[8][2];
#pragma unroll
            for (int f = 0; f < 8; f++) {
                const float* bp = Bst + (ks * 8 + tq) * BSTR + wn * 64 + f * 8 + g;
                bf[f][0] = f2tf32(bp[0]);
                bf[f][1] = f2tf32(bp[4 * BSTR]);
            }
#pragma unroll
            for (int i = 0; i < 4; i++)
#pragma unroll
                for (int f = 0; f < 8; f++)
                    mma_tf32(acc[i][f], af[i], bf[f]);
        }
        __syncthreads();
        if (c + 2 < NCH) g2_load(w2, off, row0, rlim, as_u, bs_u, tid, n1, c + 2, st);
        if (c + 1 < NCH) {
            if (c + 2 < NCH) CP_WAIT1(); else CP_WAIT0();
            __syncthreads();
        }
    }

    // epilogue: scale by gate, scatter rows to g_pairs[dst]
#pragma unroll
    for (int i = 0; i < 4; i++) {
        const int rbase = wm * 64 + i * 16 + g;
#pragma unroll
        for (int hr = 0; hr < 2; hr++) {
            const int r = rbase + hr * 8;
            if (r < rlim) {
                const int dst = s_dst[r];
                const float gt = g_gate[dst];
                float* op = g_pairs + (size_t)dst * HDIM + n1 + wn * 64;
#pragma unroll
                for (int f = 0; f < 8; f++) {
                    float2 o;
                    o.x = acc[i][f][hr * 2] * gt;
                    o.y = acc[i][f][hr * 2 + 1] * gt;
                    *(float2*)(op + f * 8 + 2 * tq) = o;
                }
            }
        }
    }
}

// ==================== combine + loss ====================
__global__ void combine_kernel(float* __restrict__ out, const float* __restrict__ bias) {
    int i = blockIdx.x * blockDim.x + threadIdx.x;
    if (i < TDIM * HDIM / 4) {
        int t = i >> 8;
        int c4 = i & 255;
        const float4* p4 = (const float4*)g_pairs;
        float4 a = p4[(size_t)(2 * t) * 256 + c4];
        float4 b = p4[(size_t)(2 * t) * 256 + 256 + c4];
        float4 bs = ((const float4*)bias)[c4];
        float4 o;
        o.x = a.x + b.x + bs.x; o.y = a.y + b.y + bs.y;
        o.z = a.z + b.z + bs.z; o.w = a.w + b.w + bs.w;
        ((float4*)out)[i] = o;
    }
}

__global__ void loss_kernel(float* __restrict__ out, int out_size) {
    if (threadIdx.x == 0 && blockIdx.x == 0) {
        float s = 0.f;
        for (int e = 0; e < EDIM; e++) s += g_psum[e] * (float)g_freq[e];
        float loss = (float)EDIM * s / ((float)TDIM * (float)(TDIM * KSEL))
                   + 0.1f * g_lsesq / (float)TDIM;
        if (out_size > TDIM * HDIM) out[TDIM * HDIM] = loss;
    }
}

// ==================== launch ====================
extern "C" void kernel_launch(void* const* d_in, const int* in_sizes, int n_in,
                              void* d_out, int out_size) {
    const float* x        = (const float*)d_in[0];
    const float* w_router = (const float*)d_in[1];
    const float* w_in     = (const float*)d_in[2];
    const float* w_out    = (const float*)d_in[3];
    const float* bias     = (const float*)d_in[4];
    float* out = (float*)d_out;

    cudaFuncSetAttribute(gemm1_mma, cudaFuncAttributeMaxDynamicSharedMemorySize, GEMM_SMEM);
    cudaFuncSetAttribute(gemm2_mma, cudaFuncAttributeMaxDynamicSharedMemorySize, GEMM_SMEM);

    zero_kernel<<<1, 32>>>();
    router_kernel<<<TDIM / 8, 256>>>(x, w_router);
    scan_kernel<<<1, 32>>>();
    scatter_kernel<<<NROWS / 256, 256>>>();

    // max rows per expert = TDIM (top-2 experts are distinct) -> 32 row tiles
    gemm1_mma<<<dim3(FDIM / 64, TDIM / 128, EDIM), 128, GEMM_SMEM>>>(x, w_in);
    gemm2_mma<<<dim3(HDIM / 128, TDIM / 128, EDIM), 128, GEMM_SMEM>>>(w_out);

    combine_kernel<<<(TDIM * HDIM / 4 + 255) / 256, 256>>>(out, bias);
    loss_kernel<<<1, 32>>>(out, out_size);
}